// round 16
// baseline (speedup 1.0000x reference)
#include <cuda_runtime.h>
#include <cuda_fp16.h>
#include <math.h>

// Problem constants
#define B_  2
#define L_  2048
#define D_  2048
#define H_  16
#define DH  128
#define BL  (B_ * L_)          // 4096
#define NEG (-1.0e9f)

// ---------------------------------------------------------------------------
// Scratch (device globals; no runtime allocation allowed)
// ---------------------------------------------------------------------------
__device__ __half g_xh[(size_t)BL * D_];
__device__ __half g_wqkvh[(size_t)D_ * 3 * D_];
__device__ __half g_wprojh[(size_t)D_ * D_];
__device__ __half g_q[(size_t)B_ * H_ * L_ * DH];
__device__ __half g_k[(size_t)B_ * H_ * L_ * DH];
__device__ __half g_v[(size_t)B_ * H_ * L_ * DH];
__device__ __half g_y[(size_t)BL * D_];
__device__ float  g_cos[L_ * 64];
__device__ float  g_sin[L_ * 64];

// ---------------------------------------------------------------------------
// K0: RoPE tables.
// ---------------------------------------------------------------------------
__global__ void rope_tables_kernel() {
    int idx = blockIdx.x * blockDim.x + threadIdx.x;
    if (idx >= L_ * 64) return;
    int l = idx >> 6;
    int i = idx & 63;
    float invf = (float)exp(-((double)i / 64.0) * log(10000.0));
    float arg  = (float)l * invf;                 // fp32 multiply like reference
    g_cos[idx] = (float)cos((double)arg);
    g_sin[idx] = (float)sin((double)arg);
}

// ---------------------------------------------------------------------------
// fp32 -> fp16 bulk convert (vectorized)
// ---------------------------------------------------------------------------
__global__ __launch_bounds__(256)
void f2h_kernel(const float* __restrict__ s, __half* __restrict__ d, int n4) {
    int i = blockIdx.x * blockDim.x + threadIdx.x;
    if (i >= n4) return;
    float4 v = ((const float4*)s)[i];
    __half2* o = (__half2*)d + 2 * (size_t)i;
    o[0] = __floats2half2_rn(v.x, v.y);
    o[1] = __floats2half2_rn(v.z, v.w);
}

// ---------------------------------------------------------------------------
// MMA / ldmatrix / async helpers
// ---------------------------------------------------------------------------
__device__ __forceinline__ void mma_f16(float (&d)[4], const unsigned (&a)[4],
                                        unsigned b0, unsigned b1) {
    asm volatile(
        "mma.sync.aligned.m16n8k16.row.col.f32.f16.f16.f32 "
        "{%0,%1,%2,%3}, {%4,%5,%6,%7}, {%8,%9}, {%0,%1,%2,%3};\n"
        : "+f"(d[0]), "+f"(d[1]), "+f"(d[2]), "+f"(d[3])
        : "r"(a[0]), "r"(a[1]), "r"(a[2]), "r"(a[3]), "r"(b0), "r"(b1));
}

__device__ __forceinline__ void ldsm_x4(unsigned addr, unsigned& r0, unsigned& r1,
                                        unsigned& r2, unsigned& r3) {
    asm volatile("ldmatrix.sync.aligned.m8n8.x4.shared.b16 {%0,%1,%2,%3}, [%4];"
                 : "=r"(r0), "=r"(r1), "=r"(r2), "=r"(r3) : "r"(addr));
}

__device__ __forceinline__ void ldsm_x4_t(unsigned addr, unsigned& r0, unsigned& r1,
                                          unsigned& r2, unsigned& r3) {
    asm volatile("ldmatrix.sync.aligned.m8n8.x4.trans.shared.b16 {%0,%1,%2,%3}, [%4];"
                 : "=r"(r0), "=r"(r1), "=r"(r2), "=r"(r3) : "r"(addr));
}

__device__ __forceinline__ unsigned smem_u32(const void* p) {
    return (unsigned)__cvta_generic_to_shared(p);
}

__device__ __forceinline__ void cp_async16(unsigned dst, const void* src) {
    asm volatile("cp.async.cg.shared.global [%0], [%1], 16;\n"
                 :: "r"(dst), "l"(src));
}

__device__ __forceinline__ void cp_async_commit() {
    asm volatile("cp.async.commit_group;\n");
}

template <int N>
__device__ __forceinline__ void cp_async_wait() {
    asm volatile("cp.async.wait_group %0;\n" :: "n"(N));
}

__device__ __forceinline__ unsigned h2u(__half2 h) {
    return *(unsigned*)&h;
}

// ---------------------------------------------------------------------------
// K1/K4: fp16 GEMM (m16n8k16), cp.async double-buffered, 2 CTAs/SM.
// FUSE_ROPE=1 (K1): N-tile == one head of q/k/v; epilogue applies RoPE via
// smem scratch (reuses stage buffers) and scatters fp16 to g_q/g_k/g_v.
// FUSE_ROPE=0 (K4): plain fp32 C output.
// ---------------------------------------------------------------------------
#define AS_H 40
#define BS_H 136
#define GEMM_STAGE_HALVES (128 * AS_H + 32 * BS_H)   // 9472
#define GEMM_SMEM_BYTES   (2 * GEMM_STAGE_HALVES * 2)
#define YS_H 136

__device__ __forceinline__ void hgemm_issue(
    __half* Ab, __half* Bb, const __half* __restrict__ A,
    const __half* __restrict__ Bm, int K, int N, int m0, int n0, int k0, int tid) {
#pragma unroll
    for (int it = 0; it < 2; it++) {
        int ca = tid + it * 256;
        cp_async16(smem_u32(Ab + (ca >> 2) * AS_H + (ca & 3) * 8),
                   A + (size_t)(m0 + (ca >> 2)) * K + k0 + (ca & 3) * 8);
        int cb = tid + it * 256;
        cp_async16(smem_u32(Bb + (cb >> 4) * BS_H + (cb & 15) * 8),
                   Bm + (size_t)(k0 + (cb >> 4)) * N + n0 + (cb & 15) * 8);
    }
    cp_async_commit();
}

template <int FUSE_ROPE>
__global__ __launch_bounds__(256, 2)
void hgemm_kernel(const __half* __restrict__ A, const __half* __restrict__ Bm,
                  float* __restrict__ C, int M, int N, int K) {
    extern __shared__ __half hsm[];
    __half* Abuf[2] = { hsm, hsm + GEMM_STAGE_HALVES };
    __half* Bbuf[2] = { hsm + 128 * AS_H, hsm + GEMM_STAGE_HALVES + 128 * AS_H };

    const int tid  = threadIdx.x;
    const int lane = tid & 31;
    const int w    = tid >> 5;
    const int gid  = lane >> 2;
    const int tig  = lane & 3;
    const int l7   = lane & 7;
    const int lg   = lane >> 3;
    const int wm   = (w >> 2) * 64;
    const int wn   = (w & 3) * 32;
    const int m0   = blockIdx.y * 128;
    const int n0   = blockIdx.x * 128;

    float acc[4][4][4];
#pragma unroll
    for (int mt = 0; mt < 4; mt++)
#pragma unroll
        for (int nt = 0; nt < 4; nt++)
#pragma unroll
            for (int i = 0; i < 4; i++) acc[mt][nt][i] = 0.0f;

    hgemm_issue(Abuf[0], Bbuf[0], A, Bm, K, N, m0, n0, 0, tid);

    const int a_row = l7 + ((lg & 1) << 3);
    const int a_col = (lg >> 1) << 3;
    const int b_row = l7 + ((lg & 1) << 3);
    const int b_col = wn + ((lg >> 1) << 3);

    const int ntiles = K / 32;
    for (int t = 0; t < ntiles; t++) {
        const int cur = t & 1;
        cp_async_wait<0>();
        __syncthreads();

        if (t + 1 < ntiles)
            hgemm_issue(Abuf[cur ^ 1], Bbuf[cur ^ 1], A, Bm, K, N,
                        m0, n0, (t + 1) * 32, tid);

        const __half* As = Abuf[cur];
        const __half* Bs = Bbuf[cur];
#pragma unroll
        for (int kk = 0; kk < 32; kk += 16) {
            unsigned af[4][4];
#pragma unroll
            for (int mt = 0; mt < 4; mt++) {
                unsigned addr = smem_u32(As + (wm + mt * 16 + a_row) * AS_H + kk + a_col);
                ldsm_x4(addr, af[mt][0], af[mt][1], af[mt][2], af[mt][3]);
            }
#pragma unroll
            for (int ntp = 0; ntp < 2; ntp++) {
                unsigned b0, b1, b2, b3;
                unsigned addr = smem_u32(Bs + (kk + b_row) * BS_H + b_col + ntp * 16);
                ldsm_x4_t(addr, b0, b1, b2, b3);
#pragma unroll
                for (int mt = 0; mt < 4; mt++) {
                    mma_f16(acc[mt][2 * ntp],     af[mt], b0, b1);
                    mma_f16(acc[mt][2 * ntp + 1], af[mt], b2, b3);
                }
            }
        }
    }

    if (FUSE_ROPE == 0) {
        // Plain epilogue (fp32 out)
#pragma unroll
        for (int mt = 0; mt < 4; mt++) {
#pragma unroll
            for (int nt = 0; nt < 4; nt++) {
                int r = m0 + wm + mt * 16 + gid;
                int c = n0 + wn + nt * 8 + tig * 2;
                float* p0 = C + (size_t)r * N + c;
                *(float2*)p0 = make_float2(acc[mt][nt][0], acc[mt][nt][1]);
                float* p1 = p0 + (size_t)8 * N;
                *(float2*)p1 = make_float2(acc[mt][nt][2], acc[mt][nt][3]);
            }
        }
        return;
    }

    // ---- Fused RoPE epilogue: this N-tile is one head of q/k/v ----
    __half* Ys = hsm;                       // reuse stage buffers as scratch
    __syncthreads();                        // all warps done with stage smem
#pragma unroll
    for (int mt = 0; mt < 4; mt++) {
#pragma unroll
        for (int nt = 0; nt < 4; nt++) {
            int r = wm + mt * 16 + gid;
            int c = wn + nt * 8 + tig * 2;
            *(__half2*)(Ys + r * YS_H + c) =
                __floats2half2_rn(acc[mt][nt][0], acc[mt][nt][1]);
            *(__half2*)(Ys + (r + 8) * YS_H + c) =
                __floats2half2_rn(acc[mt][nt][2], acc[mt][nt][3]);
        }
    }
    __syncthreads();

    const int typ  = n0 >> 11;              // 0=q, 1=k, 2=v
    const int head = (n0 & 2047) >> 7;
    const int row  = tid & 127;             // local row
    const int hs   = tid >> 7;              // which 64-col half
    const int gr   = m0 + row;
    const int b    = gr >> 11;
    const int l    = gr & 2047;

    __half* dst = (typ == 0 ? g_q : (typ == 1 ? g_k : g_v)) +
                  (((size_t)(b * H_ + head)) * L_ + l) * DH + hs * 64;
    const __half2* src  = (const __half2*)(Ys + row * YS_H + hs * 64);

    if (typ == 2) {
        // 64 halves = 8 x uint4 (BUG FIX: was 4 -> only half the V row copied)
#pragma unroll
        for (int i = 0; i < 8; i++)
            ((uint4*)dst)[i] = ((const uint4*)src)[i];
    } else {
        const __half2* part = (const __half2*)(Ys + row * YS_H + (hs ^ 1) * 64);
        const float sgn = hs ? 1.0f : -1.0f;
        const float2* cs = (const float2*)(g_cos + l * 64);
        const float2* sn = (const float2*)(g_sin + l * 64);
#pragma unroll
        for (int j = 0; j < 32; j++) {
            float2 v = __half22float2(src[j]);
            float2 p = __half22float2(part[j]);
            float2 c = cs[j], s = sn[j];
            ((__half2*)dst)[j] = __floats2half2_rn(v.x * c.x + sgn * p.x * s.x,
                                                   v.y * c.y + sgn * p.y * s.y);
        }
    }
}

// ---------------------------------------------------------------------------
// K3: causal flash attention, fp16 m16n8k16, K/V double-buffered cp.async.
// 8 warps; warp w owns q rows [w*16, w*16+16) x all 128 k-cols.
// ---------------------------------------------------------------------------
#define FLH 136
#define FL_TILE (128 * FLH)
#define SMEM_FLASH_BYTES (5 * FL_TILE * 2 + 512)

__global__ __launch_bounds__(256)
void flash_f16_kernel(const int* __restrict__ amask) {
    extern __shared__ __half fsm[];
    __half* Qs = fsm;
    __half* Kbuf[2] = { fsm + FL_TILE,     fsm + 3 * FL_TILE };
    __half* Vbuf[2] = { fsm + 2 * FL_TILE, fsm + 4 * FL_TILE };
    int* msk = (int*)(fsm + 5 * FL_TILE);

    const int tid  = threadIdx.x;
    const int lane = tid & 31;
    const int w    = tid >> 5;
    const int gid  = lane >> 2;
    const int tig  = lane & 3;
    const int l7   = lane & 7;
    const int lg   = lane >> 3;
    const int qt   = (int)gridDim.x - 1 - blockIdx.x;  // heavy tiles first
    const int bh   = blockIdx.y;
    const int b    = bh >> 4;
    const int h    = bh & 15;
    const int q0   = qt * 128;
    const int wq   = w * 16;

    const __half* Qg = g_q + ((size_t)bh * L_ + q0) * DH;
    const __half* Kg = g_k + (size_t)bh * L_ * DH;
    const __half* Vg = g_v + (size_t)bh * L_ * DH;

    // Q tile + first K/V tile, one cp.async group
#pragma unroll
    for (int it = 0; it < 8; it++) {
        int idx = tid + it * 256;
        int r   = idx >> 4;
        int c8  = idx & 15;
        cp_async16(smem_u32(Qs + r * FLH + c8 * 8), Qg + (size_t)r * DH + c8 * 8);
        cp_async16(smem_u32(Kbuf[0] + r * FLH + c8 * 8), Kg + (size_t)r * DH + c8 * 8);
        cp_async16(smem_u32(Vbuf[0] + r * FLH + c8 * 8), Vg + (size_t)r * DH + c8 * 8);
    }
    cp_async_commit();

    float oacc[16][4];
    float mprev[2], lsum[2];
#pragma unroll
    for (int dt = 0; dt < 16; dt++)
#pragma unroll
        for (int e = 0; e < 4; e++) oacc[dt][e] = 0.0f;
    mprev[0] = mprev[1] = -INFINITY;
    lsum[0] = lsum[1] = 0.0f;

    const float scale = 0.088388347648318447f;   // 1/sqrt(128)

    const int q_row = wq + l7 + ((lg & 1) << 3);
    const int q_col = (lg >> 1) << 3;
    const int k_row = l7 + ((lg >> 1) << 3);
    const int k_col = (lg & 1) << 3;
    const int v_row = l7 + ((lg & 1) << 3);
    const int v_col = (lg >> 1) << 3;

    for (int kt = 0; kt <= qt; kt++) {
        const int k0 = kt * 128;
        if (kt > 0) __syncthreads();   // all warps done with buf[(kt+1)&1]

        const bool more = (kt + 1) <= qt;
        if (more) {
            __half* Kn = Kbuf[(kt + 1) & 1];
            __half* Vn = Vbuf[(kt + 1) & 1];
            const __half* Kgn = Kg + (size_t)(k0 + 128) * DH;
            const __half* Vgn = Vg + (size_t)(k0 + 128) * DH;
#pragma unroll
            for (int it = 0; it < 8; it++) {
                int idx = tid + it * 256;
                int r   = idx >> 4;
                int c8  = idx & 15;
                cp_async16(smem_u32(Kn + r * FLH + c8 * 8), Kgn + (size_t)r * DH + c8 * 8);
                cp_async16(smem_u32(Vn + r * FLH + c8 * 8), Vgn + (size_t)r * DH + c8 * 8);
            }
            cp_async_commit();
        }
        if (tid < 128) msk[tid] = amask[b * L_ + k0 + tid];
        if (more) cp_async_wait<1>(); else cp_async_wait<0>();
        __syncthreads();

        const __half* Ks = Kbuf[kt & 1];
        const __half* Vs = Vbuf[kt & 1];

        // ---- S = Q K^T ----
        float sacc[16][4];
#pragma unroll
        for (int nt = 0; nt < 16; nt++)
#pragma unroll
            for (int e = 0; e < 4; e++) sacc[nt][e] = 0.0f;

#pragma unroll
        for (int kk = 0; kk < 128; kk += 16) {
            unsigned a[4];
            ldsm_x4(smem_u32(Qs + q_row * FLH + kk + q_col), a[0], a[1], a[2], a[3]);
#pragma unroll
            for (int ntp = 0; ntp < 8; ntp++) {
                unsigned b0, b1, b2, b3;
                ldsm_x4(smem_u32(Ks + (ntp * 16 + k_row) * FLH + kk + k_col),
                        b0, b1, b2, b3);
                mma_f16(sacc[2 * ntp],     a, b0, b1);
                mma_f16(sacc[2 * ntp + 1], a, b2, b3);
            }
        }

        // ---- scale + mask ----
        const bool diag = (kt == qt);
        const int qi0 = q0 + wq + gid;
        const int qi1 = qi0 + 8;
#pragma unroll
        for (int nt = 0; nt < 16; nt++) {
            int kjb = nt * 8 + 2 * tig;
#pragma unroll
            for (int e = 0; e < 4; e++) {
                int kj = kjb + (e & 1);
                int qi = (e < 2) ? qi0 : qi1;
                float v = sacc[nt][e] * scale;
                if ((diag && (k0 + kj) > qi) || (msk[kj] == 0)) v = NEG;
                sacc[nt][e] = v;
            }
        }

        // ---- online softmax (warp-local rows) ----
        float mx0 = -INFINITY, mx1 = -INFINITY;
#pragma unroll
        for (int nt = 0; nt < 16; nt++) {
            mx0 = fmaxf(mx0, fmaxf(sacc[nt][0], sacc[nt][1]));
            mx1 = fmaxf(mx1, fmaxf(sacc[nt][2], sacc[nt][3]));
        }
        mx0 = fmaxf(mx0, __shfl_xor_sync(0xffffffffu, mx0, 1));
        mx0 = fmaxf(mx0, __shfl_xor_sync(0xffffffffu, mx0, 2));
        mx1 = fmaxf(mx1, __shfl_xor_sync(0xffffffffu, mx1, 1));
        mx1 = fmaxf(mx1, __shfl_xor_sync(0xffffffffu, mx1, 2));

        float mn0 = fmaxf(mprev[0], mx0);
        float mn1 = fmaxf(mprev[1], mx1);
        float fac0 = __expf(mprev[0] - mn0);
        float fac1 = __expf(mprev[1] - mn1);
        mprev[0] = mn0; mprev[1] = mn1;

        float rs0 = 0.0f, rs1 = 0.0f;
#pragma unroll
        for (int nt = 0; nt < 16; nt++) {
            sacc[nt][0] = __expf(sacc[nt][0] - mn0); rs0 += sacc[nt][0];
            sacc[nt][1] = __expf(sacc[nt][1] - mn0); rs0 += sacc[nt][1];
            sacc[nt][2] = __expf(sacc[nt][2] - mn1); rs1 += sacc[nt][2];
            sacc[nt][3] = __expf(sacc[nt][3] - mn1); rs1 += sacc[nt][3];
        }
        rs0 += __shfl_xor_sync(0xffffffffu, rs0, 1);
        rs0 += __shfl_xor_sync(0xffffffffu, rs0, 2);
        rs1 += __shfl_xor_sync(0xffffffffu, rs1, 1);
        rs1 += __shfl_xor_sync(0xffffffffu, rs1, 2);
        lsum[0] = lsum[0] * fac0 + rs0;
        lsum[1] = lsum[1] * fac1 + rs1;

#pragma unroll
        for (int dt = 0; dt < 16; dt++) {
            oacc[dt][0] *= fac0; oacc[dt][1] *= fac0;
            oacc[dt][2] *= fac1; oacc[dt][3] *= fac1;
        }

        // ---- O += P V : A fragment = pairwise-packed C fragment ----
#pragma unroll
        for (int c = 0; c < 8; c++) {
            unsigned a[4];
            a[0] = h2u(__floats2half2_rn(sacc[2 * c][0],     sacc[2 * c][1]));
            a[1] = h2u(__floats2half2_rn(sacc[2 * c][2],     sacc[2 * c][3]));
            a[2] = h2u(__floats2half2_rn(sacc[2 * c + 1][0], sacc[2 * c + 1][1]));
            a[3] = h2u(__floats2half2_rn(sacc[2 * c + 1][2], sacc[2 * c + 1][3]));
#pragma unroll
            for (int dtp = 0; dtp < 8; dtp++) {
                unsigned b0, b1, b2, b3;
                ldsm_x4_t(smem_u32(Vs + (c * 16 + v_row) * FLH + dtp * 16 + v_col),
                          b0, b1, b2, b3);
                mma_f16(oacc[2 * dtp],     a, b0, b1);
                mma_f16(oacc[2 * dtp + 1], a, b2, b3);
            }
        }
    }

    // ---- epilogue: normalize, write g_y as fp16 ----
    const float inv0 = 1.0f / lsum[0];
    const float inv1 = 1.0f / lsum[1];
    const int r0 = q0 + wq + gid;
    const int r1 = r0 + 8;
#pragma unroll
    for (int dt = 0; dt < 16; dt++) {
        int col = h * DH + dt * 8 + 2 * tig;
        *(__half2*)(g_y + (size_t)(b * L_ + r0) * D_ + col) =
            __floats2half2_rn(oacc[dt][0] * inv0, oacc[dt][1] * inv0);
        *(__half2*)(g_y + (size_t)(b * L_ + r1) * D_ + col) =
            __floats2half2_rn(oacc[dt][2] * inv1, oacc[dt][3] * inv1);
    }
}

// ---------------------------------------------------------------------------
// Launcher
// ---------------------------------------------------------------------------
extern "C" void kernel_launch(void* const* d_in, const int* in_sizes, int n_in,
                              void* d_out, int out_size) {
    const float* x     = nullptr;
    const int*   am    = nullptr;
    const float* wqkv  = nullptr;
    const float* wproj = nullptr;

    for (int i = 0; i < n_in; i++) {
        switch (in_sizes[i]) {
            case BL * D_:      x     = (const float*)d_in[i]; break;
            case BL:           am    = (const int*)d_in[i];   break;
            case D_ * 3 * D_:  wqkv  = (const float*)d_in[i]; break;
            case D_ * D_:      wproj = (const float*)d_in[i]; break;
            default: break;
        }
    }
    if (!x)     x     = (const float*)d_in[0];
    if (!am)    am    = (const int*)d_in[1];
    if (!wqkv)  wqkv  = (const float*)d_in[2];
    if (!wproj) wproj = (const float*)d_in[3];

    __half* xh_p;     cudaGetSymbolAddress((void**)&xh_p,     g_xh);
    __half* wqkvh_p;  cudaGetSymbolAddress((void**)&wqkvh_p,  g_wqkvh);
    __half* wprojh_p; cudaGetSymbolAddress((void**)&wprojh_p, g_wprojh);
    __half* y_p;      cudaGetSymbolAddress((void**)&y_p,      g_y);

    cudaFuncSetAttribute(flash_f16_kernel,
                         cudaFuncAttributeMaxDynamicSharedMemorySize,
                         SMEM_FLASH_BYTES);
    cudaFuncSetAttribute(hgemm_kernel<0>,
                         cudaFuncAttributeMaxDynamicSharedMemorySize,
                         GEMM_SMEM_BYTES);
    cudaFuncSetAttribute(hgemm_kernel<1>,
                         cudaFuncAttributeMaxDynamicSharedMemorySize,
                         GEMM_SMEM_BYTES);

    // K0: RoPE tables + fp16 conversions
    rope_tables_kernel<<<(L_ * 64 + 255) / 256, 256>>>();
    f2h_kernel<<<(BL * D_ / 4 + 255) / 256, 256>>>(x, xh_p, BL * D_ / 4);
    f2h_kernel<<<(D_ * 3 * D_ / 4 + 255) / 256, 256>>>(wqkv, wqkvh_p, D_ * 3 * D_ / 4);
    f2h_kernel<<<(D_ * D_ / 4 + 255) / 256, 256>>>(wproj, wprojh_p, D_ * D_ / 4);

    // K1: qkv = x @ w_qkv with fused RoPE+split -> g_q/g_k/g_v fp16
    hgemm_kernel<1><<<dim3(3 * D_ / 128, BL / 128), 256, GEMM_SMEM_BYTES>>>(
        xh_p, wqkvh_p, nullptr, BL, 3 * D_, D_);

    // K3: causal flash attention (fp16 MMA, K/V double-buffered) -> g_y fp16
    flash_f16_kernel<<<dim3(L_ / 128, B_ * H_), 256, SMEM_FLASH_BYTES>>>(am);

    // K4: out = y @ w_proj   (4096 x 2048 x 2048), fp16 MMA
    hgemm_kernel<0><<<dim3(D_ / 128, BL / 128), 256, GEMM_SMEM_BYTES>>>(
        y_p, wprojh_p, (float*)d_out, BL, D_, D_);
}

// round 17
// speedup vs baseline: 1.1345x; 1.1345x over previous
#include <cuda_runtime.h>
#include <cuda_fp16.h>
#include <math.h>

// Problem constants
#define B_  2
#define L_  2048
#define D_  2048
#define H_  16
#define DH  128
#define BL  (B_ * L_)          // 4096
#define NEG (-1.0e9f)

// ---------------------------------------------------------------------------
// Scratch (device globals; no runtime allocation allowed)
// ---------------------------------------------------------------------------
__device__ __half g_xh[(size_t)BL * D_];
__device__ __half g_wqkvh[(size_t)D_ * 3 * D_];
__device__ __half g_wprojh[(size_t)D_ * D_];
__device__ __half g_q[(size_t)B_ * H_ * L_ * DH];
__device__ __half g_k[(size_t)B_ * H_ * L_ * DH];
__device__ __half g_v[(size_t)B_ * H_ * L_ * DH];
__device__ __half g_y[(size_t)BL * D_];
__device__ float  g_cos[L_ * 64];
__device__ float  g_sin[L_ * 64];

// ---------------------------------------------------------------------------
// K0: RoPE tables.
// ---------------------------------------------------------------------------
__global__ void rope_tables_kernel() {
    int idx = blockIdx.x * blockDim.x + threadIdx.x;
    if (idx >= L_ * 64) return;
    int l = idx >> 6;
    int i = idx & 63;
    float invf = (float)exp(-((double)i / 64.0) * log(10000.0));
    float arg  = (float)l * invf;                 // fp32 multiply like reference
    g_cos[idx] = (float)cos((double)arg);
    g_sin[idx] = (float)sin((double)arg);
}

// ---------------------------------------------------------------------------
// fp32 -> fp16 bulk convert (vectorized)
// ---------------------------------------------------------------------------
__global__ __launch_bounds__(256)
void f2h_kernel(const float* __restrict__ s, __half* __restrict__ d, int n4) {
    int i = blockIdx.x * blockDim.x + threadIdx.x;
    if (i >= n4) return;
    float4 v = ((const float4*)s)[i];
    __half2* o = (__half2*)d + 2 * (size_t)i;
    o[0] = __floats2half2_rn(v.x, v.y);
    o[1] = __floats2half2_rn(v.z, v.w);
}

// ---------------------------------------------------------------------------
// MMA / ldmatrix / async helpers
// ---------------------------------------------------------------------------
__device__ __forceinline__ void mma_f16(float (&d)[4], const unsigned (&a)[4],
                                        unsigned b0, unsigned b1) {
    asm volatile(
        "mma.sync.aligned.m16n8k16.row.col.f32.f16.f16.f32 "
        "{%0,%1,%2,%3}, {%4,%5,%6,%7}, {%8,%9}, {%0,%1,%2,%3};\n"
        : "+f"(d[0]), "+f"(d[1]), "+f"(d[2]), "+f"(d[3])
        : "r"(a[0]), "r"(a[1]), "r"(a[2]), "r"(a[3]), "r"(b0), "r"(b1));
}

__device__ __forceinline__ void ldsm_x4(unsigned addr, unsigned& r0, unsigned& r1,
                                        unsigned& r2, unsigned& r3) {
    asm volatile("ldmatrix.sync.aligned.m8n8.x4.shared.b16 {%0,%1,%2,%3}, [%4];"
                 : "=r"(r0), "=r"(r1), "=r"(r2), "=r"(r3) : "r"(addr));
}

__device__ __forceinline__ void ldsm_x4_t(unsigned addr, unsigned& r0, unsigned& r1,
                                          unsigned& r2, unsigned& r3) {
    asm volatile("ldmatrix.sync.aligned.m8n8.x4.trans.shared.b16 {%0,%1,%2,%3}, [%4];"
                 : "=r"(r0), "=r"(r1), "=r"(r2), "=r"(r3) : "r"(addr));
}

__device__ __forceinline__ unsigned smem_u32(const void* p) {
    return (unsigned)__cvta_generic_to_shared(p);
}

__device__ __forceinline__ void cp_async16(unsigned dst, const void* src) {
    asm volatile("cp.async.cg.shared.global [%0], [%1], 16;\n"
                 :: "r"(dst), "l"(src));
}

__device__ __forceinline__ void cp_async_commit() {
    asm volatile("cp.async.commit_group;\n");
}

template <int N>
__device__ __forceinline__ void cp_async_wait() {
    asm volatile("cp.async.wait_group %0;\n" :: "n"(N));
}

__device__ __forceinline__ unsigned h2u(__half2 h) {
    return *(unsigned*)&h;
}

// ---------------------------------------------------------------------------
// K1/K4: fp16 GEMM (m16n8k16), cp.async double-buffered, 2 CTAs/SM.
// FUSE_ROPE=1 (K1): N-tile == one head of q/k/v; epilogue applies RoPE via
// smem scratch and scatters fp16 to g_q/g_k/g_v with COALESCED uint4 stores
// (lanes cover consecutive 16B chunks within a row).
// FUSE_ROPE=0 (K4): plain fp32 C output.
// ---------------------------------------------------------------------------
#define AS_H 40
#define BS_H 136
#define GEMM_STAGE_HALVES (128 * AS_H + 32 * BS_H)   // 9472
#define GEMM_SMEM_BYTES   (2 * GEMM_STAGE_HALVES * 2)
#define YS_H 136

__device__ __forceinline__ void hgemm_issue(
    __half* Ab, __half* Bb, const __half* __restrict__ A,
    const __half* __restrict__ Bm, int K, int N, int m0, int n0, int k0, int tid) {
#pragma unroll
    for (int it = 0; it < 2; it++) {
        int ca = tid + it * 256;
        cp_async16(smem_u32(Ab + (ca >> 2) * AS_H + (ca & 3) * 8),
                   A + (size_t)(m0 + (ca >> 2)) * K + k0 + (ca & 3) * 8);
        int cb = tid + it * 256;
        cp_async16(smem_u32(Bb + (cb >> 4) * BS_H + (cb & 15) * 8),
                   Bm + (size_t)(k0 + (cb >> 4)) * N + n0 + (cb & 15) * 8);
    }
    cp_async_commit();
}

template <int FUSE_ROPE>
__global__ __launch_bounds__(256, 2)
void hgemm_kernel(const __half* __restrict__ A, const __half* __restrict__ Bm,
                  float* __restrict__ C, int M, int N, int K) {
    extern __shared__ __half hsm[];
    __half* Abuf[2] = { hsm, hsm + GEMM_STAGE_HALVES };
    __half* Bbuf[2] = { hsm + 128 * AS_H, hsm + GEMM_STAGE_HALVES + 128 * AS_H };

    const int tid  = threadIdx.x;
    const int lane = tid & 31;
    const int w    = tid >> 5;
    const int gid  = lane >> 2;
    const int tig  = lane & 3;
    const int l7   = lane & 7;
    const int lg   = lane >> 3;
    const int wm   = (w >> 2) * 64;
    const int wn   = (w & 3) * 32;
    const int m0   = blockIdx.y * 128;
    const int n0   = blockIdx.x * 128;

    float acc[4][4][4];
#pragma unroll
    for (int mt = 0; mt < 4; mt++)
#pragma unroll
        for (int nt = 0; nt < 4; nt++)
#pragma unroll
            for (int i = 0; i < 4; i++) acc[mt][nt][i] = 0.0f;

    hgemm_issue(Abuf[0], Bbuf[0], A, Bm, K, N, m0, n0, 0, tid);

    const int a_row = l7 + ((lg & 1) << 3);
    const int a_col = (lg >> 1) << 3;
    const int b_row = l7 + ((lg & 1) << 3);
    const int b_col = wn + ((lg >> 1) << 3);

    const int ntiles = K / 32;
    for (int t = 0; t < ntiles; t++) {
        const int cur = t & 1;
        cp_async_wait<0>();
        __syncthreads();

        if (t + 1 < ntiles)
            hgemm_issue(Abuf[cur ^ 1], Bbuf[cur ^ 1], A, Bm, K, N,
                        m0, n0, (t + 1) * 32, tid);

        const __half* As = Abuf[cur];
        const __half* Bs = Bbuf[cur];
#pragma unroll
        for (int kk = 0; kk < 32; kk += 16) {
            unsigned af[4][4];
#pragma unroll
            for (int mt = 0; mt < 4; mt++) {
                unsigned addr = smem_u32(As + (wm + mt * 16 + a_row) * AS_H + kk + a_col);
                ldsm_x4(addr, af[mt][0], af[mt][1], af[mt][2], af[mt][3]);
            }
#pragma unroll
            for (int ntp = 0; ntp < 2; ntp++) {
                unsigned b0, b1, b2, b3;
                unsigned addr = smem_u32(Bs + (kk + b_row) * BS_H + b_col + ntp * 16);
                ldsm_x4_t(addr, b0, b1, b2, b3);
#pragma unroll
                for (int mt = 0; mt < 4; mt++) {
                    mma_f16(acc[mt][2 * ntp],     af[mt], b0, b1);
                    mma_f16(acc[mt][2 * ntp + 1], af[mt], b2, b3);
                }
            }
        }
    }

    if (FUSE_ROPE == 0) {
        // Plain epilogue (fp32 out)
#pragma unroll
        for (int mt = 0; mt < 4; mt++) {
#pragma unroll
            for (int nt = 0; nt < 4; nt++) {
                int r = m0 + wm + mt * 16 + gid;
                int c = n0 + wn + nt * 8 + tig * 2;
                float* p0 = C + (size_t)r * N + c;
                *(float2*)p0 = make_float2(acc[mt][nt][0], acc[mt][nt][1]);
                float* p1 = p0 + (size_t)8 * N;
                *(float2*)p1 = make_float2(acc[mt][nt][2], acc[mt][nt][3]);
            }
        }
        return;
    }

    // ---- Fused RoPE epilogue: this N-tile is one head of q/k/v ----
    __half* Ys = hsm;                       // reuse stage buffers as scratch
    __syncthreads();                        // all warps done with stage smem
#pragma unroll
    for (int mt = 0; mt < 4; mt++) {
#pragma unroll
        for (int nt = 0; nt < 4; nt++) {
            int r = wm + mt * 16 + gid;
            int c = wn + nt * 8 + tig * 2;
            *(__half2*)(Ys + r * YS_H + c) =
                __floats2half2_rn(acc[mt][nt][0], acc[mt][nt][1]);
            *(__half2*)(Ys + (r + 8) * YS_H + c) =
                __floats2half2_rn(acc[mt][nt][2], acc[mt][nt][3]);
        }
    }
    __syncthreads();

    const int typ  = n0 >> 11;              // 0=q, 1=k, 2=v
    const int head = (n0 & 2047) >> 7;
    __half* gbase = (typ == 0 ? g_q : (typ == 1 ? g_k : g_v));

    // Coalesced scatter: idx -> (row, 16B chunk). Consecutive lanes write
    // consecutive 16B chunks of the same row -> full STG.128 coalescing.
#pragma unroll
    for (int it = 0; it < 8; it++) {
        int idx = tid + it * 256;           // 2048 = 128 rows x 16 chunks
        int row = idx >> 4;
        int c8  = idx & 15;
        int gr  = m0 + row;
        int bb  = gr >> 11;
        int l   = gr & 2047;
        __half* dst = gbase + (((size_t)(bb * H_ + head)) * L_ + l) * DH + c8 * 8;
        const __half2* src = (const __half2*)(Ys + row * YS_H + c8 * 8);

        if (typ == 2) {
            *(uint4*)dst = *(const uint4*)src;
        } else {
            const int dd0 = c8 * 8;
            const __half2* part = (const __half2*)(Ys + row * YS_H + (dd0 ^ 64));
            const float sgn = (dd0 < 64) ? -1.0f : 1.0f;
            const int fi = dd0 & 63;
            const float2* cs = (const float2*)(g_cos + l * 64 + fi);
            const float2* sn = (const float2*)(g_sin + l * 64 + fi);
            __half2 out[4];
#pragma unroll
            for (int j = 0; j < 4; j++) {
                float2 v = __half22float2(src[j]);
                float2 p = __half22float2(part[j]);
                float2 c = cs[j], s = sn[j];
                out[j] = __floats2half2_rn(v.x * c.x + sgn * p.x * s.x,
                                           v.y * c.y + sgn * p.y * s.y);
            }
            *(uint4*)dst = *(uint4*)out;
        }
    }
}

// ---------------------------------------------------------------------------
// K3: causal flash attention, fp16 m16n8k16, K/V double-buffered cp.async.
// 8 warps; warp w owns q rows [w*16, w*16+16) x all 128 k-cols.
// ---------------------------------------------------------------------------
#define FLH 136
#define FL_TILE (128 * FLH)
#define SMEM_FLASH_BYTES (5 * FL_TILE * 2 + 512)

__global__ __launch_bounds__(256)
void flash_f16_kernel(const int* __restrict__ amask) {
    extern __shared__ __half fsm[];
    __half* Qs = fsm;
    __half* Kbuf[2] = { fsm + FL_TILE,     fsm + 3 * FL_TILE };
    __half* Vbuf[2] = { fsm + 2 * FL_TILE, fsm + 4 * FL_TILE };
    int* msk = (int*)(fsm + 5 * FL_TILE);

    const int tid  = threadIdx.x;
    const int lane = tid & 31;
    const int w    = tid >> 5;
    const int gid  = lane >> 2;
    const int tig  = lane & 3;
    const int l7   = lane & 7;
    const int lg   = lane >> 3;
    const int qt   = (int)gridDim.x - 1 - blockIdx.x;  // heavy tiles first
    const int bh   = blockIdx.y;
    const int b    = bh >> 4;
    const int h    = bh & 15;
    const int q0   = qt * 128;
    const int wq   = w * 16;

    const __half* Qg = g_q + ((size_t)bh * L_ + q0) * DH;
    const __half* Kg = g_k + (size_t)bh * L_ * DH;
    const __half* Vg = g_v + (size_t)bh * L_ * DH;

    // Q tile + first K/V tile, one cp.async group
#pragma unroll
    for (int it = 0; it < 8; it++) {
        int idx = tid + it * 256;
        int r   = idx >> 4;
        int c8  = idx & 15;
        cp_async16(smem_u32(Qs + r * FLH + c8 * 8), Qg + (size_t)r * DH + c8 * 8);
        cp_async16(smem_u32(Kbuf[0] + r * FLH + c8 * 8), Kg + (size_t)r * DH + c8 * 8);
        cp_async16(smem_u32(Vbuf[0] + r * FLH + c8 * 8), Vg + (size_t)r * DH + c8 * 8);
    }
    cp_async_commit();

    float oacc[16][4];
    float mprev[2], lsum[2];
#pragma unroll
    for (int dt = 0; dt < 16; dt++)
#pragma unroll
        for (int e = 0; e < 4; e++) oacc[dt][e] = 0.0f;
    mprev[0] = mprev[1] = -INFINITY;
    lsum[0] = lsum[1] = 0.0f;

    const float scale = 0.088388347648318447f;   // 1/sqrt(128)

    const int q_row = wq + l7 + ((lg & 1) << 3);
    const int q_col = (lg >> 1) << 3;
    const int k_row = l7 + ((lg >> 1) << 3);
    const int k_col = (lg & 1) << 3;
    const int v_row = l7 + ((lg & 1) << 3);
    const int v_col = (lg >> 1) << 3;

    for (int kt = 0; kt <= qt; kt++) {
        const int k0 = kt * 128;
        if (kt > 0) __syncthreads();   // all warps done with buf[(kt+1)&1]

        const bool more = (kt + 1) <= qt;
        if (more) {
            __half* Kn = Kbuf[(kt + 1) & 1];
            __half* Vn = Vbuf[(kt + 1) & 1];
            const __half* Kgn = Kg + (size_t)(k0 + 128) * DH;
            const __half* Vgn = Vg + (size_t)(k0 + 128) * DH;
#pragma unroll
            for (int it = 0; it < 8; it++) {
                int idx = tid + it * 256;
                int r   = idx >> 4;
                int c8  = idx & 15;
                cp_async16(smem_u32(Kn + r * FLH + c8 * 8), Kgn + (size_t)r * DH + c8 * 8);
                cp_async16(smem_u32(Vn + r * FLH + c8 * 8), Vgn + (size_t)r * DH + c8 * 8);
            }
            cp_async_commit();
        }
        if (tid < 128) msk[tid] = amask[b * L_ + k0 + tid];
        if (more) cp_async_wait<1>(); else cp_async_wait<0>();
        __syncthreads();

        const __half* Ks = Kbuf[kt & 1];
        const __half* Vs = Vbuf[kt & 1];

        // ---- S = Q K^T ----
        float sacc[16][4];
#pragma unroll
        for (int nt = 0; nt < 16; nt++)
#pragma unroll
            for (int e = 0; e < 4; e++) sacc[nt][e] = 0.0f;

#pragma unroll
        for (int kk = 0; kk < 128; kk += 16) {
            unsigned a[4];
            ldsm_x4(smem_u32(Qs + q_row * FLH + kk + q_col), a[0], a[1], a[2], a[3]);
#pragma unroll
            for (int ntp = 0; ntp < 8; ntp++) {
                unsigned b0, b1, b2, b3;
                ldsm_x4(smem_u32(Ks + (ntp * 16 + k_row) * FLH + kk + k_col),
                        b0, b1, b2, b3);
                mma_f16(sacc[2 * ntp],     a, b0, b1);
                mma_f16(sacc[2 * ntp + 1], a, b2, b3);
            }
        }

        // ---- scale + mask ----
        const bool diag = (kt == qt);
        const int qi0 = q0 + wq + gid;
        const int qi1 = qi0 + 8;
#pragma unroll
        for (int nt = 0; nt < 16; nt++) {
            int kjb = nt * 8 + 2 * tig;
#pragma unroll
            for (int e = 0; e < 4; e++) {
                int kj = kjb + (e & 1);
                int qi = (e < 2) ? qi0 : qi1;
                float v = sacc[nt][e] * scale;
                if ((diag && (k0 + kj) > qi) || (msk[kj] == 0)) v = NEG;
                sacc[nt][e] = v;
            }
        }

        // ---- online softmax (warp-local rows) ----
        float mx0 = -INFINITY, mx1 = -INFINITY;
#pragma unroll
        for (int nt = 0; nt < 16; nt++) {
            mx0 = fmaxf(mx0, fmaxf(sacc[nt][0], sacc[nt][1]));
            mx1 = fmaxf(mx1, fmaxf(sacc[nt][2], sacc[nt][3]));
        }
        mx0 = fmaxf(mx0, __shfl_xor_sync(0xffffffffu, mx0, 1));
        mx0 = fmaxf(mx0, __shfl_xor_sync(0xffffffffu, mx0, 2));
        mx1 = fmaxf(mx1, __shfl_xor_sync(0xffffffffu, mx1, 1));
        mx1 = fmaxf(mx1, __shfl_xor_sync(0xffffffffu, mx1, 2));

        float mn0 = fmaxf(mprev[0], mx0);
        float mn1 = fmaxf(mprev[1], mx1);
        float fac0 = __expf(mprev[0] - mn0);
        float fac1 = __expf(mprev[1] - mn1);
        mprev[0] = mn0; mprev[1] = mn1;

        float rs0 = 0.0f, rs1 = 0.0f;
#pragma unroll
        for (int nt = 0; nt < 16; nt++) {
            sacc[nt][0] = __expf(sacc[nt][0] - mn0); rs0 += sacc[nt][0];
            sacc[nt][1] = __expf(sacc[nt][1] - mn0); rs0 += sacc[nt][1];
            sacc[nt][2] = __expf(sacc[nt][2] - mn1); rs1 += sacc[nt][2];
            sacc[nt][3] = __expf(sacc[nt][3] - mn1); rs1 += sacc[nt][3];
        }
        rs0 += __shfl_xor_sync(0xffffffffu, rs0, 1);
        rs0 += __shfl_xor_sync(0xffffffffu, rs0, 2);
        rs1 += __shfl_xor_sync(0xffffffffu, rs1, 1);
        rs1 += __shfl_xor_sync(0xffffffffu, rs1, 2);
        lsum[0] = lsum[0] * fac0 + rs0;
        lsum[1] = lsum[1] * fac1 + rs1;

#pragma unroll
        for (int dt = 0; dt < 16; dt++) {
            oacc[dt][0] *= fac0; oacc[dt][1] *= fac0;
            oacc[dt][2] *= fac1; oacc[dt][3] *= fac1;
        }

        // ---- O += P V : A fragment = pairwise-packed C fragment ----
#pragma unroll
        for (int c = 0; c < 8; c++) {
            unsigned a[4];
            a[0] = h2u(__floats2half2_rn(sacc[2 * c][0],     sacc[2 * c][1]));
            a[1] = h2u(__floats2half2_rn(sacc[2 * c][2],     sacc[2 * c][3]));
            a[2] = h2u(__floats2half2_rn(sacc[2 * c + 1][0], sacc[2 * c + 1][1]));
            a[3] = h2u(__floats2half2_rn(sacc[2 * c + 1][2], sacc[2 * c + 1][3]));
#pragma unroll
            for (int dtp = 0; dtp < 8; dtp++) {
                unsigned b0, b1, b2, b3;
                ldsm_x4_t(smem_u32(Vs + (c * 16 + v_row) * FLH + dtp * 16 + v_col),
                          b0, b1, b2, b3);
                mma_f16(oacc[2 * dtp],     a, b0, b1);
                mma_f16(oacc[2 * dtp + 1], a, b2, b3);
            }
        }
    }

    // ---- epilogue: normalize, write g_y as fp16 ----
    const float inv0 = 1.0f / lsum[0];
    const float inv1 = 1.0f / lsum[1];
    const int r0 = q0 + wq + gid;
    const int r1 = r0 + 8;
#pragma unroll
    for (int dt = 0; dt < 16; dt++) {
        int col = h * DH + dt * 8 + 2 * tig;
        *(__half2*)(g_y + (size_t)(b * L_ + r0) * D_ + col) =
            __floats2half2_rn(oacc[dt][0] * inv0, oacc[dt][1] * inv0);
        *(__half2*)(g_y + (size_t)(b * L_ + r1) * D_ + col) =
            __floats2half2_rn(oacc[dt][2] * inv1, oacc[dt][3] * inv1);
    }
}

// ---------------------------------------------------------------------------
// Launcher
// ---------------------------------------------------------------------------
extern "C" void kernel_launch(void* const* d_in, const int* in_sizes, int n_in,
                              void* d_out, int out_size) {
    const float* x     = nullptr;
    const int*   am    = nullptr;
    const float* wqkv  = nullptr;
    const float* wproj = nullptr;

    for (int i = 0; i < n_in; i++) {
        switch (in_sizes[i]) {
            case BL * D_:      x     = (const float*)d_in[i]; break;
            case BL:           am    = (const int*)d_in[i];   break;
            case D_ * 3 * D_:  wqkv  = (const float*)d_in[i]; break;
            case D_ * D_:      wproj = (const float*)d_in[i]; break;
            default: break;
        }
    }
    if (!x)     x     = (const float*)d_in[0];
    if (!am)    am    = (const int*)d_in[1];
    if (!wqkv)  wqkv  = (const float*)d_in[2];
    if (!wproj) wproj = (const float*)d_in[3];

    __half* xh_p;     cudaGetSymbolAddress((void**)&xh_p,     g_xh);
    __half* wqkvh_p;  cudaGetSymbolAddress((void**)&wqkvh_p,  g_wqkvh);
    __half* wprojh_p; cudaGetSymbolAddress((void**)&wprojh_p, g_wprojh);
    __half* y_p;      cudaGetSymbolAddress((void**)&y_p,      g_y);

    cudaFuncSetAttribute(flash_f16_kernel,
                         cudaFuncAttributeMaxDynamicSharedMemorySize,
                         SMEM_FLASH_BYTES);
    cudaFuncSetAttribute(hgemm_kernel<0>,
                         cudaFuncAttributeMaxDynamicSharedMemorySize,
                         GEMM_SMEM_BYTES);
    cudaFuncSetAttribute(hgemm_kernel<1>,
                         cudaFuncAttributeMaxDynamicSharedMemorySize,
                         GEMM_SMEM_BYTES);

    // K0: RoPE tables + fp16 conversions
    rope_tables_kernel<<<(L_ * 64 + 255) / 256, 256>>>();
    f2h_kernel<<<(BL * D_ / 4 + 255) / 256, 256>>>(x, xh_p, BL * D_ / 4);
    f2h_kernel<<<(D_ * 3 * D_ / 4 + 255) / 256, 256>>>(wqkv, wqkvh_p, D_ * 3 * D_ / 4);
    f2h_kernel<<<(D_ * D_ / 4 + 255) / 256, 256>>>(wproj, wprojh_p, D_ * D_ / 4);

    // K1: qkv = x @ w_qkv with fused RoPE+split -> g_q/g_k/g_v fp16
    hgemm_kernel<1><<<dim3(3 * D_ / 128, BL / 128), 256, GEMM_SMEM_BYTES>>>(
        xh_p, wqkvh_p, nullptr, BL, 3 * D_, D_);

    // K3: causal flash attention (fp16 MMA, K/V double-buffered) -> g_y fp16
    flash_f16_kernel<<<dim3(L_ / 128, B_ * H_), 256, SMEM_FLASH_BYTES>>>(am);

    // K4: out = y @ w_proj   (4096 x 2048 x 2048), fp16 MMA
    hgemm_kernel<0><<<dim3(D_ / 128, BL / 128), 256, GEMM_SMEM_BYTES>>>(
        y_p, wprojh_p, (float*)d_out, BL, D_, D_);
}